// round 3
// baseline (speedup 1.0000x reference)
#include <cuda_runtime.h>
#include <cstdint>

#define K_DIM 4096
#define N_DIM 4096
#define BM 128
#define BN 128
#define BK 32
#define PAD 36            // padded row stride in floats (bank-conflict-free: (4r+c) mod 32 bijection)
#define ASZ (BM * PAD)    // floats per buffer per matrix

// 64 MB scratch for the transformed weight (device global: allocation-free)
__device__ float g_qw[(size_t)N_DIM * K_DIM];

// ---------------------------------------------------------------------------
// Kernel 1: qw = quantize/retention/endurance transform of weight
// ---------------------------------------------------------------------------
__global__ void qw_kernel(const float* __restrict__ w,
                          const float* __restrict__ alpha,
                          const int* __restrict__ wc) {
    size_t i = (size_t)blockIdx.x * blockDim.x + threadIdx.x;
    const size_t n = (size_t)N_DIM * K_DIM;
    if (i >= n) return;
    const float a = alpha[0];
    const float decay = expf(-0.001f);

    float tv = 4.5f * (1.0f + w[i] * a);
    // nearest of {3.5,4.0,4.5,5.0,5.5}; tie -> lower index (matches argmin-first)
    int idx = (tv > 3.75f) + (tv > 4.25f) + (tv > 4.75f) + (tv > 5.25f);
    float qv = 3.5f + 0.5f * (float)idx;
    float q = (qv / 4.5f - 1.0f) / a;
    q *= decay;
    float d = (float)wc[i];
    d = d / 1e8f;
    d = d * 0.1f;
    d = fminf(fmaxf(d, 0.0f), 0.5f);
    g_qw[i] = q * (1.0f - d);
}

// ---------------------------------------------------------------------------
// Kernel 2: y[M,N] = x[M,K] @ qw[N,K]^T   (TF32 mma.sync, 128x128x32 tiles)
// ---------------------------------------------------------------------------
__device__ __forceinline__ uint32_t f2tf(float f) {
    uint32_t r;
    asm("cvt.rna.tf32.f32 %0, %1;" : "=r"(r) : "f"(f));
    return r;
}

__device__ __forceinline__ void cpa16(uint32_t s, const void* g) {
    asm volatile("cp.async.cg.shared.global [%0], [%1], 16;" :: "r"(s), "l"(g));
}

__global__ __launch_bounds__(256)
void gemm_kernel(const float* __restrict__ X, float* __restrict__ Y, int M) {
    extern __shared__ float smem[];
    const int tid   = threadIdx.x;
    const int lane  = tid & 31;
    const int warp  = tid >> 5;
    const int warpM = warp >> 2;   // 0..1 -> m offset 64
    const int warpN = warp & 3;    // 0..3 -> n offset 32
    const int mBase = blockIdx.y * BM;
    const int nBase = blockIdx.x * BN;

    float* shA = smem;              // 2 buffers of ASZ
    float* shB = smem + 2 * ASZ;    // 2 buffers of ASZ

    // global-load mapping: each thread moves 4x16B per matrix per tile
    const int ldr = tid >> 3;           // 0..31 (row group)
    const int ldc = (tid & 7) * 4;      // float col 0,4,..,28

    const float* Ag = X + (size_t)mBase * K_DIM;
    const float* Bg = g_qw + (size_t)nBase * K_DIM;

    const uint32_t sA = (uint32_t)__cvta_generic_to_shared(shA);
    const uint32_t sB = (uint32_t)__cvta_generic_to_shared(shB);

    float c[4][4][4];
#pragma unroll
    for (int i = 0; i < 4; i++)
#pragma unroll
        for (int j = 0; j < 4; j++)
#pragma unroll
            for (int r = 0; r < 4; r++) c[i][j][r] = 0.0f;

    auto prefetch = [&](int kt, int buf) {
        const int kOff = kt * BK;
        const uint32_t sAb = sA + buf * ASZ * 4;
        const uint32_t sBb = sB + buf * ASZ * 4;
#pragma unroll
        for (int i = 0; i < 4; i++) {
            const int row = ldr + 32 * i;
            cpa16(sAb + (row * PAD + ldc) * 4, Ag + (size_t)row * K_DIM + kOff + ldc);
            cpa16(sBb + (row * PAD + ldc) * 4, Bg + (size_t)row * K_DIM + kOff + ldc);
        }
        asm volatile("cp.async.commit_group;");
    };

    const int KT = K_DIM / BK;   // 128
    prefetch(0, 0);
    asm volatile("cp.async.wait_group 0;");
    __syncthreads();

    // conflict-free fragment bases (see PAD comment)
    const float* aB0 = shA + (warpM * 64 + (lane >> 2)) * PAD + (lane & 3);
    const float* bB0 = shB + (warpN * 32 + (lane >> 2)) * PAD + (lane & 3);

    for (int kt = 0; kt < KT; ++kt) {
        const int buf = kt & 1;
        if (kt + 1 < KT) prefetch(kt + 1, buf ^ 1);
        const float* aB = aB0 + buf * ASZ;
        const float* bB = bB0 + buf * ASZ;

#pragma unroll
        for (int kk = 0; kk < 4; ++kk) {
            uint32_t a[4][4], b[4][2];
#pragma unroll
            for (int i = 0; i < 4; i++) {
                const float* p = aB + i * 16 * PAD + kk * 8;
                a[i][0] = f2tf(p[0]);
                a[i][1] = f2tf(p[8 * PAD]);
                a[i][2] = f2tf(p[4]);
                a[i][3] = f2tf(p[8 * PAD + 4]);
            }
#pragma unroll
            for (int j = 0; j < 4; j++) {
                const float* p = bB + j * 8 * PAD + kk * 8;
                b[j][0] = f2tf(p[0]);
                b[j][1] = f2tf(p[4]);
            }
#pragma unroll
            for (int i = 0; i < 4; i++)
#pragma unroll
                for (int j = 0; j < 4; j++)
                    asm volatile(
                        "mma.sync.aligned.m16n8k8.row.col.f32.tf32.tf32.f32 "
                        "{%0,%1,%2,%3}, {%4,%5,%6,%7}, {%8,%9}, {%0,%1,%2,%3};"
                        : "+f"(c[i][j][0]), "+f"(c[i][j][1]),
                          "+f"(c[i][j][2]), "+f"(c[i][j][3])
                        : "r"(a[i][0]), "r"(a[i][1]), "r"(a[i][2]), "r"(a[i][3]),
                          "r"(b[j][0]), "r"(b[j][1]));
        }

        asm volatile("cp.async.wait_group 0;");
        __syncthreads();
    }

    // epilogue: direct global writes
#pragma unroll
    for (int i = 0; i < 4; i++) {
        const int r0 = mBase + warpM * 64 + i * 16 + (lane >> 2);
#pragma unroll
        for (int j = 0; j < 4; j++) {
            const int c0 = nBase + warpN * 32 + j * 8 + (lane & 3) * 2;
            *(float2*)(Y + (size_t)r0 * N_DIM + c0)       = make_float2(c[i][j][0], c[i][j][1]);
            *(float2*)(Y + (size_t)(r0 + 8) * N_DIM + c0) = make_float2(c[i][j][2], c[i][j][3]);
        }
    }
}

// ---------------------------------------------------------------------------
// Launch
// ---------------------------------------------------------------------------
extern "C" void kernel_launch(void* const* d_in, const int* in_sizes, int n_in,
                              void* d_out, int out_size) {
    const float* x     = (const float*)d_in[0];       // [8,2048,4096] fp32
    const float* w     = (const float*)d_in[1];       // [4096,4096] fp32
    const float* alpha = (const float*)d_in[2];       // [1] fp32
    const int*   wc    = (const int*)d_in[3];         // [4096,4096] int32 (jax x64 disabled)
    float*       y     = (float*)d_out;               // [8,2048,4096] fp32

    const int M = in_sizes[0] / K_DIM;   // 16384

    {
        const size_t n = (size_t)N_DIM * K_DIM;
        const int threads = 256;
        const int blocks = (int)((n + threads - 1) / threads);
        qw_kernel<<<blocks, threads>>>(w, alpha, wc);
    }

    const int smem_bytes = 4 * ASZ * 4;   // 73728
    cudaFuncSetAttribute(gemm_kernel, cudaFuncAttributeMaxDynamicSharedMemorySize, smem_bytes);
    dim3 grid(N_DIM / BN, M / BM);
    gemm_kernel<<<grid, 256, smem_bytes>>>(x, y, M);
}

// round 6
// speedup vs baseline: 2.0770x; 2.0770x over previous
#include <cuda_runtime.h>
#include <cuda_fp16.h>
#include <cstdint>

#define K_DIM 4096
#define N_DIM 4096
#define BM 256
#define BN 128
#define BK 32                       // halfs of K per stage
#define KT (K_DIM / BK)             // 128
#define STAGES 4
#define SROW 40                     // halfs per smem row (80B stride: 16B-aligned, conflict-free)
#define A_BYTES (BM * SROW * 2)     // 20480
#define B_BYTES (BN * SROW * 2)     // 10240
#define STAGE_BYTES (A_BYTES + B_BYTES)
#define SMEM_BYTES (STAGES * STAGE_BYTES)   // 122880

// device-global scratch (allocation-free)
__device__ __half g_qwh[(size_t)N_DIM * K_DIM];          // 32 MB
__device__ __half g_xh[(size_t)16384 * K_DIM];           // 128 MB

// ---------------------------------------------------------------------------
// Kernel 1: qw transform -> fp16
// ---------------------------------------------------------------------------
__global__ void qw_kernel(const float4* __restrict__ w,
                          const float* __restrict__ alpha,
                          const int4* __restrict__ wc,
                          __half2* __restrict__ out) {
    size_t i = (size_t)blockIdx.x * blockDim.x + threadIdx.x;
    const size_t n4 = (size_t)N_DIM * K_DIM / 4;
    if (i >= n4) return;
    const float a = alpha[0];
    const float decay = expf(-0.001f);
    float4 wv = w[i];
    int4 cv = wc[i];
    float wa[4] = {wv.x, wv.y, wv.z, wv.w};
    int ca[4] = {cv.x, cv.y, cv.z, cv.w};
    float r[4];
#pragma unroll
    for (int j = 0; j < 4; j++) {
        float tv = 4.5f * (1.0f + wa[j] * a);
        // nearest of {3.5,4.0,4.5,5.0,5.5}; tie -> lower index (argmin-first)
        int idx = (tv > 3.75f) + (tv > 4.25f) + (tv > 4.75f) + (tv > 5.25f);
        float qv = 3.5f + 0.5f * (float)idx;
        float q = (qv / 4.5f - 1.0f) / a;
        q *= decay;
        float d = (float)ca[j];
        d = d / 1e8f * 0.1f;
        d = fminf(fmaxf(d, 0.0f), 0.5f);
        r[j] = q * (1.0f - d);
    }
    out[i * 2]     = __floats2half2_rn(r[0], r[1]);
    out[i * 2 + 1] = __floats2half2_rn(r[2], r[3]);
}

// ---------------------------------------------------------------------------
// Kernel 2: x -> fp16
// ---------------------------------------------------------------------------
__global__ void xh_kernel(const float4* __restrict__ x, __half2* __restrict__ out,
                          size_t n4) {
    size_t i = (size_t)blockIdx.x * blockDim.x + threadIdx.x;
    if (i >= n4) return;
    float4 v = x[i];
    out[i * 2]     = __floats2half2_rn(v.x, v.y);
    out[i * 2 + 1] = __floats2half2_rn(v.z, v.w);
}

// ---------------------------------------------------------------------------
// Kernel 3: y[M,N] = xh[M,K] @ qwh[N,K]^T   fp16 mma.sync m16n8k16
// 256x128 CTA tile, 512 threads (16 warps of 64x32), 4-stage cp.async
// ---------------------------------------------------------------------------
__device__ __forceinline__ void ldsm4(uint32_t* r, uint32_t addr) {
    asm volatile("ldmatrix.sync.aligned.m8n8.x4.shared.b16 {%0,%1,%2,%3}, [%4];"
                 : "=r"(r[0]), "=r"(r[1]), "=r"(r[2]), "=r"(r[3]) : "r"(addr));
}

__global__ __launch_bounds__(512, 1)
void gemm_fp16(const __half* __restrict__ A, const __half* __restrict__ B,
               float* __restrict__ Y) {
    extern __shared__ char smem[];
    const uint32_t sbase = (uint32_t)__cvta_generic_to_shared(smem);
    const int tid   = threadIdx.x;
    const int lane  = tid & 31;
    const int warp  = tid >> 5;
    const int warpM = warp >> 2;          // 0..3 -> 64-row band
    const int warpN = warp & 3;           // 0..3 -> 32-col band
    const int mBase = blockIdx.y * BM;
    const int nBase = blockIdx.x * BN;

    const __half* gA = A + (size_t)mBase * K_DIM;
    const __half* gB = B + (size_t)nBase * K_DIM;

    // cp.async mapping: 1536 16B chunks per stage; thread does 3 (2 A + 1 B)
    const int aRow = tid >> 2;            // with +128 for second A chunk set
    const int aC   = (tid & 3) * 16;      // byte col within 64B row
    // frag base offsets (bytes within stage)
    const uint32_t aFrag = (uint32_t)((warpM * 64 + (lane & 15)) * (SROW * 2)
                                      + ((lane >> 4) & 1) * 16);
    const uint32_t bFrag = (uint32_t)(A_BYTES
                                      + (warpN * 32 + ((lane & 7) | ((lane >> 1) & 8))) * (SROW * 2)
                                      + ((lane >> 3) & 1) * 16);

    auto prefetch = [&](int t) {
        if (t < KT) {
            const uint32_t s = sbase + (t % STAGES) * STAGE_BYTES;
            const __half* gAk = gA + t * BK;
            const __half* gBk = gB + t * BK;
#pragma unroll
            for (int i = 0; i < 2; i++) {
                int row = aRow + i * 128;
                asm volatile("cp.async.cg.shared.global [%0], [%1], 16;"
                             :: "r"(s + row * (SROW * 2) + aC),
                                "l"((const char*)(gAk + (size_t)row * K_DIM) + aC));
            }
            {
                int row = tid >> 2;
                asm volatile("cp.async.cg.shared.global [%0], [%1], 16;"
                             :: "r"(s + A_BYTES + row * (SROW * 2) + aC),
                                "l"((const char*)(gBk + (size_t)row * K_DIM) + aC));
            }
        }
        asm volatile("cp.async.commit_group;");
    };

    float c[4][4][4];
#pragma unroll
    for (int i = 0; i < 4; i++)
#pragma unroll
        for (int j = 0; j < 4; j++)
#pragma unroll
            for (int r = 0; r < 4; r++) c[i][j][r] = 0.0f;

    prefetch(0); prefetch(1); prefetch(2);

    for (int kt = 0; kt < KT; kt++) {
        asm volatile("cp.async.wait_group 2;");
        __syncthreads();
        prefetch(kt + STAGES - 1);

        const uint32_t s = sbase + (kt % STAGES) * STAGE_BYTES;
#pragma unroll
        for (int ks = 0; ks < 2; ks++) {
            const uint32_t kb = ks * 32;
            uint32_t a[4][4], b[2][4];
#pragma unroll
            for (int mt = 0; mt < 4; mt++)
                ldsm4(a[mt], s + aFrag + mt * (16 * SROW * 2) + kb);
#pragma unroll
            for (int np = 0; np < 2; np++)
                ldsm4(b[np], s + bFrag + np * (16 * SROW * 2) + kb);
#pragma unroll
            for (int mt = 0; mt < 4; mt++)
#pragma unroll
                for (int nt = 0; nt < 4; nt++) {
                    uint32_t b0 = b[nt >> 1][(nt & 1) * 2];
                    uint32_t b1 = b[nt >> 1][(nt & 1) * 2 + 1];
                    asm volatile(
                        "mma.sync.aligned.m16n8k16.row.col.f32.f16.f16.f32 "
                        "{%0,%1,%2,%3}, {%4,%5,%6,%7}, {%8,%9}, {%0,%1,%2,%3};"
                        : "+f"(c[mt][nt][0]), "+f"(c[mt][nt][1]),
                          "+f"(c[mt][nt][2]), "+f"(c[mt][nt][3])
                        : "r"(a[mt][0]), "r"(a[mt][1]), "r"(a[mt][2]), "r"(a[mt][3]),
                          "r"(b0), "r"(b1));
                }
        }
        // loop-end: next iteration's wait+sync protects stage reuse
    }

    // epilogue
#pragma unroll
    for (int mt = 0; mt < 4; mt++) {
        const int r0 = mBase + warpM * 64 + mt * 16 + (lane >> 2);
#pragma unroll
        for (int nt = 0; nt < 4; nt++) {
            const int col = nBase + warpN * 32 + nt * 8 + (lane & 3) * 2;
            *(float2*)(Y + (size_t)r0 * N_DIM + col) =
                make_float2(c[mt][nt][0], c[mt][nt][1]);
            *(float2*)(Y + (size_t)(r0 + 8) * N_DIM + col) =
                make_float2(c[mt][nt][2], c[mt][nt][3]);
        }
    }
}

// ---------------------------------------------------------------------------
// Launch
// ---------------------------------------------------------------------------
extern "C" void kernel_launch(void* const* d_in, const int* in_sizes, int n_in,
                              void* d_out, int out_size) {
    const float* x     = (const float*)d_in[0];   // [8,2048,4096] fp32
    const float* w     = (const float*)d_in[1];   // [4096,4096] fp32
    const float* alpha = (const float*)d_in[2];   // [1] fp32
    const int*   wc    = (const int*)d_in[3];     // [4096,4096] int32
    float*       y     = (float*)d_out;           // [8,2048,4096] fp32

    const int M = in_sizes[0] / K_DIM;            // 16384

    __half *qwh = nullptr, *xh = nullptr;
    cudaGetSymbolAddress((void**)&qwh, g_qwh);
    cudaGetSymbolAddress((void**)&xh, g_xh);

    {   // qw transform -> fp16
        const size_t n4 = (size_t)N_DIM * K_DIM / 4;
        qw_kernel<<<(int)((n4 + 255) / 256), 256>>>(
            (const float4*)w, alpha, (const int4*)wc, (__half2*)qwh);
    }
    {   // x -> fp16
        const size_t n4 = (size_t)M * K_DIM / 4;
        xh_kernel<<<(int)((n4 + 255) / 256), 256>>>(
            (const float4*)x, (__half2*)xh, n4);
    }

    cudaFuncSetAttribute(gemm_fp16, cudaFuncAttributeMaxDynamicSharedMemorySize,
                         SMEM_BYTES);
    dim3 grid(N_DIM / BN, M / BM);    // (32, 64), x-fastest: qwh (32MB) L2-resident
    gemm_fp16<<<grid, 512, SMEM_BYTES>>>(xh, qwh, y);
}

// round 7
// speedup vs baseline: 2.2995x; 1.1071x over previous
#include <cuda_runtime.h>
#include <cuda_fp16.h>
#include <cstdint>

#define K_DIM 4096
#define N_DIM 4096
#define BM 128
#define BN 128
#define BK 64                        // halfs of K per stage
#define KT (K_DIM / BK)              // 64
#define STAGES 3
#define SROWB 144                    // bytes per smem row (16B-aligned, odd*16 -> LDSM conflict-free)
#define A_BYTES (BM * SROWB)         // 18432
#define B_BYTES (BN * SROWB)         // 18432
#define STAGE_BYTES (A_BYTES + B_BYTES)
#define SMEM_BYTES (STAGES * STAGE_BYTES)   // 110592

// device-global scratch (allocation-free)
__device__ __half g_qwh[(size_t)N_DIM * K_DIM];          // 32 MB
__device__ __half g_xh[(size_t)16384 * K_DIM];           // 128 MB

// ---------------------------------------------------------------------------
// Kernel 1: qw transform -> fp16
// ---------------------------------------------------------------------------
__global__ void qw_kernel(const float4* __restrict__ w,
                          const float* __restrict__ alpha,
                          const int4* __restrict__ wc,
                          __half2* __restrict__ out) {
    size_t i = (size_t)blockIdx.x * blockDim.x + threadIdx.x;
    const size_t n4 = (size_t)N_DIM * K_DIM / 4;
    if (i >= n4) return;
    const float a = alpha[0];
    const float decay = expf(-0.001f);
    float4 wv = w[i];
    int4 cv = wc[i];
    float wa[4] = {wv.x, wv.y, wv.z, wv.w};
    int ca[4] = {cv.x, cv.y, cv.z, cv.w};
    float r[4];
#pragma unroll
    for (int j = 0; j < 4; j++) {
        float tv = 4.5f * (1.0f + wa[j] * a);
        // nearest of {3.5,4.0,4.5,5.0,5.5}; tie -> lower index (argmin-first)
        int idx = (tv > 3.75f) + (tv > 4.25f) + (tv > 4.75f) + (tv > 5.25f);
        float qv = 3.5f + 0.5f * (float)idx;
        float q = (qv / 4.5f - 1.0f) / a;
        q *= decay;
        float d = (float)ca[j];
        d = d / 1e8f * 0.1f;
        d = fminf(fmaxf(d, 0.0f), 0.5f);
        r[j] = q * (1.0f - d);
    }
    out[i * 2]     = __floats2half2_rn(r[0], r[1]);
    out[i * 2 + 1] = __floats2half2_rn(r[2], r[3]);
}

// ---------------------------------------------------------------------------
// Kernel 2: x -> fp16
// ---------------------------------------------------------------------------
__global__ void xh_kernel(const float4* __restrict__ x, __half2* __restrict__ out,
                          size_t n4) {
    size_t i = (size_t)blockIdx.x * blockDim.x + threadIdx.x;
    if (i >= n4) return;
    float4 v = x[i];
    out[i * 2]     = __floats2half2_rn(v.x, v.y);
    out[i * 2 + 1] = __floats2half2_rn(v.z, v.w);
}

// ---------------------------------------------------------------------------
// Kernel 3: y[M,N] = xh[M,K] @ qwh[N,K]^T   fp16 mma.sync m16n8k16
// 128x128 CTA tile, 256 threads (8 warps of 64x32), 3-stage BK=64, 2 CTAs/SM
// ---------------------------------------------------------------------------
__device__ __forceinline__ void ldsm4(uint32_t* r, uint32_t addr) {
    asm volatile("ldmatrix.sync.aligned.m8n8.x4.shared.b16 {%0,%1,%2,%3}, [%4];"
                 : "=r"(r[0]), "=r"(r[1]), "=r"(r[2]), "=r"(r[3]) : "r"(addr));
}

__global__ __launch_bounds__(256, 2)
void gemm_fp16(const __half* __restrict__ A, const __half* __restrict__ B,
               float* __restrict__ Y) {
    extern __shared__ char smem[];
    const uint32_t sbase = (uint32_t)__cvta_generic_to_shared(smem);
    const int tid   = threadIdx.x;
    const int lane  = tid & 31;
    const int warp  = tid >> 5;
    const int warpM = warp >> 2;          // 0..1 -> 64-row band
    const int warpN = warp & 3;           // 0..3 -> 32-col band
    const int mBase = blockIdx.y * BM;
    const int nBase = blockIdx.x * BN;

    const __half* gA = A + (size_t)mBase * K_DIM;
    const __half* gB = B + (size_t)nBase * K_DIM;

    // cp.async mapping: 1024 chunks of 16B per matrix per stage; 4 per thread
    const int ldRow = tid >> 3;           // 0..31 (+32*i)
    const int ldC16 = tid & 7;            // 16B unit within 128B of row data

    // fragment base offsets (bytes within stage)
    const uint32_t aFrag = (uint32_t)((warpM * 64 + (lane & 15)) * SROWB
                                      + ((lane >> 4) & 1) * 16);
    const uint32_t bFrag = (uint32_t)(A_BYTES
                                      + (warpN * 32 + ((lane & 7) | ((lane >> 1) & 8))) * SROWB
                                      + ((lane >> 3) & 1) * 16);

    auto prefetch = [&](int t) {
        if (t < KT) {
            const uint32_t s = sbase + (t % STAGES) * STAGE_BYTES;
            const __half* gAk = gA + t * BK;
            const __half* gBk = gB + t * BK;
#pragma unroll
            for (int i = 0; i < 4; i++) {
                int row = ldRow + i * 32;
                asm volatile("cp.async.cg.shared.global [%0], [%1], 16;"
                             :: "r"(s + row * SROWB + ldC16 * 16),
                                "l"((const char*)(gAk + (size_t)row * K_DIM) + ldC16 * 16));
            }
#pragma unroll
            for (int i = 0; i < 4; i++) {
                int row = ldRow + i * 32;
                asm volatile("cp.async.cg.shared.global [%0], [%1], 16;"
                             :: "r"(s + A_BYTES + row * SROWB + ldC16 * 16),
                                "l"((const char*)(gBk + (size_t)row * K_DIM) + ldC16 * 16));
            }
        }
        asm volatile("cp.async.commit_group;");
    };

    float c[4][4][4];
#pragma unroll
    for (int i = 0; i < 4; i++)
#pragma unroll
        for (int j = 0; j < 4; j++)
#pragma unroll
            for (int r = 0; r < 4; r++) c[i][j][r] = 0.0f;

    prefetch(0); prefetch(1);

    for (int kt = 0; kt < KT; kt++) {
        asm volatile("cp.async.wait_group 1;");
        __syncthreads();
        prefetch(kt + 2);

        const uint32_t s = sbase + (kt % STAGES) * STAGE_BYTES;
#pragma unroll
        for (int ks = 0; ks < 4; ks++) {
            const uint32_t kb = ks * 32;        // 16 halves of K per step
            uint32_t a[4][4], b[2][4];
#pragma unroll
            for (int mt = 0; mt < 4; mt++)
                ldsm4(a[mt], s + aFrag + mt * (16 * SROWB) + kb);
#pragma unroll
            for (int np = 0; np < 2; np++)
                ldsm4(b[np], s + bFrag + np * (16 * SROWB) + kb);
#pragma unroll
            for (int mt = 0; mt < 4; mt++)
#pragma unroll
                for (int nt = 0; nt < 4; nt++) {
                    uint32_t b0 = b[nt >> 1][(nt & 1) * 2];
                    uint32_t b1 = b[nt >> 1][(nt & 1) * 2 + 1];
                    asm volatile(
                        "mma.sync.aligned.m16n8k16.row.col.f32.f16.f16.f32 "
                        "{%0,%1,%2,%3}, {%4,%5,%6,%7}, {%8,%9}, {%0,%1,%2,%3};"
                        : "+f"(c[mt][nt][0]), "+f"(c[mt][nt][1]),
                          "+f"(c[mt][nt][2]), "+f"(c[mt][nt][3])
                        : "r"(a[mt][0]), "r"(a[mt][1]), "r"(a[mt][2]), "r"(a[mt][3]),
                          "r"(b0), "r"(b1));
                }
        }
    }

    // epilogue
#pragma unroll
    for (int mt = 0; mt < 4; mt++) {
        const int r0 = mBase + warpM * 64 + mt * 16 + (lane >> 2);
#pragma unroll
        for (int nt = 0; nt < 4; nt++) {
            const int col = nBase + warpN * 32 + nt * 8 + (lane & 3) * 2;
            *(float2*)(Y + (size_t)r0 * N_DIM + col) =
                make_float2(c[mt][nt][0], c[mt][nt][1]);
            *(float2*)(Y + (size_t)(r0 + 8) * N_DIM + col) =
                make_float2(c[mt][nt][2], c[mt][nt][3]);
        }
    }
}

// ---------------------------------------------------------------------------
// Launch
// ---------------------------------------------------------------------------
extern "C" void kernel_launch(void* const* d_in, const int* in_sizes, int n_in,
                              void* d_out, int out_size) {
    const float* x     = (const float*)d_in[0];   // [8,2048,4096] fp32
    const float* w     = (const float*)d_in[1];   // [4096,4096] fp32
    const float* alpha = (const float*)d_in[2];   // [1] fp32
    const int*   wc    = (const int*)d_in[3];     // [4096,4096] int32
    float*       y     = (float*)d_out;           // [8,2048,4096] fp32

    const int M = in_sizes[0] / K_DIM;            // 16384

    __half *qwh = nullptr, *xh = nullptr;
    cudaGetSymbolAddress((void**)&qwh, g_qwh);
    cudaGetSymbolAddress((void**)&xh, g_xh);

    {   // qw transform -> fp16
        const size_t n4 = (size_t)N_DIM * K_DIM / 4;
        qw_kernel<<<(int)((n4 + 255) / 256), 256>>>(
            (const float4*)w, alpha, (const int4*)wc, (__half2*)qwh);
    }
    {   // x -> fp16
        const size_t n4 = (size_t)M * K_DIM / 4;
        xh_kernel<<<(int)((n4 + 255) / 256), 256>>>(
            (const float4*)x, (__half2*)xh, n4);
    }

    cudaFuncSetAttribute(gemm_fp16, cudaFuncAttributeMaxDynamicSharedMemorySize,
                         SMEM_BYTES);
    dim3 grid(N_DIM / BN, M / BM);    // (32, 128), x-fastest: qwh (32MB) L2-resident
    gemm_fp16<<<grid, 256, SMEM_BYTES>>>(xh, qwh, y);
}